// round 1
// baseline (speedup 1.0000x reference)
#include <cuda_runtime.h>
#include <math.h>

#define NN  50000
#define EE  800000
#define IND 128
#define HD  64
#define NC  256     // 4 gates * 64
#define KMAX 384    // 128(x) + 128(Tx) + 64(h) + 64(Th)
#define BM  64
#define BK  16

// ---- device scratch (no allocations allowed) ----
__device__ __align__(16) float g_deg[NN];        // degree, then dinv in-place
__device__ __align__(16) float g_Tx[NN * IND];
__device__ __align__(16) float g_Th[NN * HD];
__device__ __align__(16) float g_B[KMAX * NC];   // packed weights, h-side rows last
__device__ __align__(16) float g_bias[NC];       // bx + bh + bg per column
__device__ int g_hzero;                          // 1 if h input is all zeros

// ---------------------------------------------------------------------------
__global__ void k_init() { g_hzero = 1; }

__global__ void k_flag(const float4* __restrict__ h) {
    int i = blockIdx.x * blockDim.x + threadIdx.x;
    if (i < NN * HD / 4) {
        float4 v = h[i];
        if (v.x != 0.f || v.y != 0.f || v.z != 0.f || v.w != 0.f) g_hzero = 0;
    }
}

__global__ void k_zero() {
    const int T1 = NN / 4;
    const int T2 = T1 + NN * IND / 4;
    const int T3 = T2 + NN * HD / 4;
    int i = blockIdx.x * blockDim.x + threadIdx.x;
    float4 z = make_float4(0.f, 0.f, 0.f, 0.f);
    if (i < T1)       ((float4*)g_deg)[i] = z;
    else if (i < T2)  ((float4*)g_Tx)[i - T1] = z;
    else if (i < T3)  { if (!g_hzero) ((float4*)g_Th)[i - T2] = z; }
}

// Pack weights into B[d][g*64+j]; rows: [0,128) x·Wx[:,0], [128,256) Tx·Wx[:,1],
// [256,320) h·Wh[:,0], [320,384) Th·Wh[:,1]. Bias folds bx+bh+bg.
__global__ void k_pack(const float* __restrict__ Wx, const float* __restrict__ bx,
                       const float* __restrict__ Wh, const float* __restrict__ bh,
                       const float* __restrict__ bg) {
    int idx = blockIdx.x * blockDim.x + threadIdx.x;
    if (idx < KMAX * NC) {
        int d = idx / NC, c = idx % NC, g = c / HD, j = c % HD;
        float v;
        if (d < 128)      v = Wx[((g * 2 + 0) * 128 + d) * 64 + j];
        else if (d < 256) v = Wx[((g * 2 + 1) * 128 + (d - 128)) * 64 + j];
        else if (d < 320) v = Wh[((g * 2 + 0) * 64 + (d - 256)) * 64 + j];
        else              v = Wh[((g * 2 + 1) * 64 + (d - 320)) * 64 + j];
        g_B[idx] = v;
    }
    if (idx < NC) g_bias[idx] = bx[idx] + bh[idx] + bg[idx];
}

__global__ void k_deg(const int* __restrict__ ei, const float* __restrict__ ew) {
    int e = blockIdx.x * blockDim.x + threadIdx.x;
    if (e < EE) atomicAdd(&g_deg[ei[e]], ew[e]);
}

__global__ void k_dinv() {
    int i = blockIdx.x * blockDim.x + threadIdx.x;
    if (i < NN) {
        float d = g_deg[i];
        g_deg[i] = (d > 0.f) ? rsqrtf(d) : 0.f;
    }
}

// One warp per edge: norm = -dinv[src]*ew*dinv[dst]; scatter-add norm*x[src]
// into Tx[dst] (vector float4 red). Skips Th pass entirely when h == 0.
__global__ void k_prop(const float* __restrict__ x, const float* __restrict__ h,
                       const int* __restrict__ ei, const float* __restrict__ ew) {
    int w    = (blockIdx.x * blockDim.x + threadIdx.x) >> 5;
    int lane = threadIdx.x & 31;
    if (w >= EE) return;
    int s = 0, d = 0; float nrm = 0.f;
    if (lane == 0) {
        s = ei[w]; d = ei[EE + w];
        nrm = -g_deg[s] * ew[w] * g_deg[d];
    }
    s   = __shfl_sync(0xffffffffu, s, 0);
    d   = __shfl_sync(0xffffffffu, d, 0);
    nrm = __shfl_sync(0xffffffffu, nrm, 0);

    float4 v = ((const float4*)(x + (size_t)s * IND))[lane];
    float4 r = make_float4(nrm * v.x, nrm * v.y, nrm * v.z, nrm * v.w);
    atomicAdd(((float4*)(g_Tx + (size_t)d * IND)) + lane, r);

    if (!g_hzero && lane < 16) {
        float4 hv = ((const float4*)(h + (size_t)s * HD))[lane];
        float4 hr = make_float4(nrm * hv.x, nrm * hv.y, nrm * hv.z, nrm * hv.w);
        atomicAdd(((float4*)(g_Th + (size_t)d * HD)) + lane, hr);
    }
}

// Fused GEMM (z = [x|Tx|h|Th] @ B + bias) + LSTM cell epilogue.
// Block tile: 64 nodes x 256 cols; thread tile: 8 nodes x 8 cols where the 8
// cols are {g*64 + tc*2 + jj : g in 0..3, jj in 0..1} so each thread owns the
// matching i/f/g/o lanes and finishes the cell in registers.
__global__ void __launch_bounds__(256) k_gemm(
    const float* __restrict__ x, const float* __restrict__ h,
    const float* __restrict__ c_in, const float* __restrict__ wc,
    float* __restrict__ out, int out_size) {
    __shared__ float As[BK][BM];
    __shared__ float Bs[BK][NC];

    int tid = threadIdx.x;
    int tc  = tid & 31;   // col group: j-pair index
    int tr  = tid >> 5;   // row group
    int m0  = blockIdx.x * BM;
    int am  = tid >> 2;          // node row for A staging
    int ak  = (tid & 3) * 4;     // k offset (float4) within chunk

    float acc[8][8];
#pragma unroll
    for (int r = 0; r < 8; r++)
#pragma unroll
        for (int t = 0; t < 8; t++) acc[r][t] = 0.f;

    const int Keff = g_hzero ? 256 : KMAX;

    for (int kc = 0; kc < Keff; kc += BK) {
        // --- stage A chunk (segmented source) ---
        const float* sp; int sw, so;
        if (kc < 128)      { sp = x;    sw = IND; so = kc; }
        else if (kc < 256) { sp = g_Tx; sw = IND; so = kc - 128; }
        else if (kc < 320) { sp = h;    sw = HD;  so = kc - 256; }
        else               { sp = g_Th; sw = HD;  so = kc - 320; }
        int node = m0 + am;
        float4 av = make_float4(0.f, 0.f, 0.f, 0.f);
        if (node < NN) av = *(const float4*)(sp + (size_t)node * sw + so + ak);
        As[ak + 0][am] = av.x; As[ak + 1][am] = av.y;
        As[ak + 2][am] = av.z; As[ak + 3][am] = av.w;

        // --- stage B chunk ---
#pragma unroll
        for (int p = 0; p < 4; p++) {
            int idx = p * 256 + tid;
            int bk = idx >> 6;
            int bc = (idx & 63) * 4;
            *(float4*)&Bs[bk][bc] = *(const float4*)&g_B[(kc + bk) * NC + bc];
        }
        __syncthreads();

#pragma unroll
        for (int kk = 0; kk < BK; kk++) {
            float a[8];
            *(float4*)(a)     = *(const float4*)&As[kk][tr * 8];
            *(float4*)(a + 4) = *(const float4*)&As[kk][tr * 8 + 4];
            float b[8];
#pragma unroll
            for (int g = 0; g < 4; g++) {
                float2 bv = *(const float2*)&Bs[kk][g * 64 + tc * 2];
                b[g * 2] = bv.x; b[g * 2 + 1] = bv.y;
            }
#pragma unroll
            for (int r = 0; r < 8; r++)
#pragma unroll
                for (int t = 0; t < 8; t++)
                    acc[r][t] += a[r] * b[t];
        }
        __syncthreads();
    }

    // --- epilogue: LSTM cell per (node, j) ---
    float bias[8];
#pragma unroll
    for (int g = 0; g < 4; g++) {
        float2 bv = *(const float2*)&g_bias[g * 64 + tc * 2];
        bias[g * 2] = bv.x; bias[g * 2 + 1] = bv.y;
    }
    float wc0[2], wc1[2], wc2[2];
    {
        float2 a0 = *(const float2*)&wc[0 * HD + tc * 2];
        float2 a1 = *(const float2*)&wc[1 * HD + tc * 2];
        float2 a2 = *(const float2*)&wc[2 * HD + tc * 2];
        wc0[0] = a0.x; wc0[1] = a0.y;
        wc1[0] = a1.x; wc1[1] = a1.y;
        wc2[0] = a2.x; wc2[1] = a2.y;
    }

#pragma unroll
    for (int r = 0; r < 8; r++) {
        int node = m0 + tr * 8 + r;
        if (node >= NN) continue;
#pragma unroll
        for (int jj = 0; jj < 2; jj++) {
            int j = tc * 2 + jj;
            float cv = c_in[(size_t)node * HD + j];
            float zi = acc[r][0 + jj] + bias[0 + jj] + wc0[jj] * cv;
            float zf = acc[r][2 + jj] + bias[2 + jj] + wc1[jj] * cv;
            float zg = acc[r][4 + jj] + bias[4 + jj];
            float zo = acc[r][6 + jj] + bias[6 + jj];
            float iv = 1.f / (1.f + expf(-zi));
            float fv = 1.f / (1.f + expf(-zf));
            float gv = tanhf(zg);
            float cn = fv * cv + iv * gv;
            float ov = 1.f / (1.f + expf(-(zo + wc2[jj] * cn)));
            float hn = ov * tanhf(cn);
            size_t ih = (size_t)NN + (size_t)node * HD + j;            // h_new slot
            size_t ic = (size_t)NN + (size_t)NN * HD + (size_t)node * HD + j; // c_new
            if (ih < (size_t)out_size) out[ih] = hn;
            if (ic < (size_t)out_size) out[ic] = cn;
        }
    }
}

// out[n] = leaky_relu(h_new[n]) . W_head + b_head   (one warp per node)
__global__ void k_head(const float* __restrict__ Whead, const float* __restrict__ bhead,
                       float* __restrict__ out, int out_size) {
    int w    = (blockIdx.x * blockDim.x + threadIdx.x) >> 5;
    int lane = threadIdx.x & 31;
    if (w >= NN) return;
    const float* hrow = out + NN + (size_t)w * HD;
    float v0 = hrow[lane];
    float v1 = hrow[32 + lane];
    v0 = v0 > 0.f ? v0 : 0.01f * v0;
    v1 = v1 > 0.f ? v1 : 0.01f * v1;
    float s = v0 * Whead[lane] + v1 * Whead[32 + lane];
#pragma unroll
    for (int o = 16; o; o >>= 1) s += __shfl_xor_sync(0xffffffffu, s, o);
    if (lane == 0 && w < out_size) out[w] = s + bhead[0];
}

// ---------------------------------------------------------------------------
extern "C" void kernel_launch(void* const* d_in, const int* in_sizes, int n_in,
                              void* d_out, int out_size) {
    const float* x     = (const float*)d_in[0];
    const int*   ei    = (const int*)  d_in[1];
    const float* ew    = (const float*)d_in[2];
    const float* h     = (const float*)d_in[3];
    const float* c     = (const float*)d_in[4];
    const float* Wx    = (const float*)d_in[5];
    const float* bx    = (const float*)d_in[6];
    const float* Wh    = (const float*)d_in[7];
    const float* bh    = (const float*)d_in[8];
    const float* wc    = (const float*)d_in[9];
    const float* bg    = (const float*)d_in[10];
    const float* Whead = (const float*)d_in[11];
    const float* bhead = (const float*)d_in[12];
    float* out = (float*)d_out;
    (void)in_sizes; (void)n_in;

    k_init<<<1, 1>>>();
    k_flag<<<(NN * HD / 4 + 255) / 256, 256>>>((const float4*)h);
    {
        int total4 = (NN + NN * IND + NN * HD) / 4;
        k_zero<<<(total4 + 255) / 256, 256>>>();
    }
    k_pack<<<(KMAX * NC + 255) / 256, 256>>>(Wx, bx, Wh, bh, bg);
    k_deg<<<(EE + 255) / 256, 256>>>(ei, ew);
    k_dinv<<<(NN + 255) / 256, 256>>>();
    k_prop<<<EE / 8, 256>>>(x, h, ei, ew);
    k_gemm<<<(NN + BM - 1) / BM, 256>>>(x, h, c, wc, out, out_size);
    k_head<<<(NN * 32 + 255) / 256, 256>>>(Whead, bhead, out, out_size);
}